// round 15
// baseline (speedup 1.0000x reference)
#include <cuda_runtime.h>
#include <cuda_fp16.h>
#include <math.h>
#include <stdint.h>

typedef unsigned long long u64;
typedef unsigned int u32;

#define BB  4
#define NXX 512
#define NYY 512
#define DVV 32
#define KXX 64
#define KYY 64
#define PI_F 3.14159265358979323846f

#define SW128(o) ((o) ^ (((o) >> 3) & 0x70))

__device__ __forceinline__ u32 smem_u32(const void* p) {
    u32 a;
    asm("{ .reg .u64 t; cvta.to.shared.u64 t, %1; cvt.u32.u64 %0, t; }" : "=r"(a) : "l"(p));
    return a;
}
__device__ __forceinline__ void ldsm_x4(u32* r, u32 addr) {
    asm volatile("ldmatrix.sync.aligned.m8n8.x4.shared.b16 {%0,%1,%2,%3}, [%4];"
                 : "=r"(r[0]), "=r"(r[1]), "=r"(r[2]), "=r"(r[3]) : "r"(addr));
}
__device__ __forceinline__ void ldsm_x2(u32* r, u32 addr) {
    asm volatile("ldmatrix.sync.aligned.m8n8.x2.shared.b16 {%0,%1}, [%2];"
                 : "=r"(r[0]), "=r"(r[1]) : "r"(addr));
}
__device__ __forceinline__ void mma_f16(float* d, const u32* a, const u32* b) {
    asm volatile("mma.sync.aligned.m16n8k16.row.col.f32.f16.f16.f32 "
                 "{%0,%1,%2,%3}, {%4,%5,%6,%7}, {%8,%9}, {%0,%1,%2,%3};"
                 : "+f"(d[0]), "+f"(d[1]), "+f"(d[2]), "+f"(d[3])
                 : "r"(a[0]), "r"(a[1]), "r"(a[2]), "r"(a[3]), "r"(b[0]), "r"(b[1]));
}
// fp16 hi/lo split of a pair: hp = rn(f16) pair; lp = rn(v - h) pair.
__device__ __forceinline__ void split_pair_f16(float v0, float v1, u32 &hp, u32 &lp) {
    asm("cvt.rn.f16x2.f32 %0, %1, %2;" : "=r"(hp) : "f"(v1), "f"(v0));
    __half2 h2 = *reinterpret_cast<__half2*>(&hp);
    float l0 = v0 - __low2float(h2);
    float l1 = v1 - __high2float(h2);
    asm("cvt.rn.f16x2.f32 %0, %1, %2;" : "=r"(lp) : "f"(l1), "f"(l0));
}

// fp16 B operands as smem tile images (SW128 rows)
__device__ __align__(16) char g_B1h[KYY*NYY*2];     // step1: 8 chunks [64 ky][64 ny]
__device__ __align__(16) char g_Bth[NYY*KYY*2];     // step5: 8 passes [64 ny][64 ky]
__device__ __align__(16) char g_B2h[2*KXX*NXX*2];   // step2: 8 chunks [128 (kx r|i)][64 nx]
__device__ __align__(16) char g_B4rh[NXX*KXX*2];    // step4: 8 passes [64 nx][64 kx] real
__device__ __align__(16) char g_B4ih[NXX*KXX*2];    // step4: imag

// Scratch
__device__ __align__(16) float g_S1 [(size_t)BB*NXX*KYY*DVV];  // step1 partial z=0
__device__ __align__(16) float g_S1b[(size_t)BB*NXX*KYY*DVV];  // step1 partial z=1
__device__ __align__(16) float g_S2r [(size_t)BB*KXX*KYY*DVV]; // step2 split-K partials
__device__ __align__(16) float g_S2i [(size_t)BB*KXX*KYY*DVV];
__device__ __align__(16) float g_S2r2[(size_t)BB*KXX*KYY*DVV];
__device__ __align__(16) float g_S2i2[(size_t)BB*KXX*KYY*DVV];
__device__ __align__(16) float g_S3r[(size_t)BB*KYY*KXX*DVV];  // [b][ky][kx][dv]
__device__ __align__(16) float g_S3i[(size_t)BB*KYY*KXX*DVV];
__device__ __align__(16) float g_S4 [(size_t)BB*NXX*KYY*DVV];  // real-contraction partial
__device__ __align__(16) float g_S4b[(size_t)BB*NXX*KYY*DVV];  // imag-contraction partial

// ---------------------------------------------------------------------------
__global__ void k_precompute() {
    int idx = blockIdx.x * blockDim.x + threadIdx.x;
    if (idx >= KXX * NXX) return;
    int k = idx >> 9;          // 0..63
    int n = idx & 511;         // 0..511

    float sk = (k == 0) ? sqrtf(1.0f / 512.0f) : sqrtf(2.0f / 512.0f);
    int m = (k * (2 * n + 1)) & 2047;
    float mm1 = (float)((m > 1024) ? (2048 - m) : m);
    float Ckn = sk * cosf(PI_F * mm1 / 1024.0f);
    {
        __half h = __float2half_rn(Ckn);
        u32 byte1 = (u32)(n >> 6) * 8192 + SW128((u32)(k * 128 + (n & 63) * 2));
        *(__half*)(g_B1h + byte1) = h;
        u32 byte5 = SW128((u32)(n * 128 + k * 2));
        *(__half*)(g_Bth + byte5) = h;
    }

    int mm = (k * n) & 511;
    float ang = 2.0f * PI_F * (float)mm / 512.0f;
    float isq = sqrtf(1.0f / 512.0f);
    float s, c;
    sincosf(ang, &s, &c);
    float fr = c * isq;
    float fi = -s * isq;
    float ck = (k == 0) ? 1.0f : 2.0f;

    {
        u32 cb = (u32)(n >> 6) * 16384;
        u32 br = cb + SW128((u32)(k * 128 + (n & 63) * 2));
        *(__half*)(g_B2h + br) = __float2half_rn(fr);
        u32 bi = cb + SW128((u32)((64 + k) * 128 + (n & 63) * 2));
        *(__half*)(g_B2h + bi) = __float2half_rn(fi);
    }
    {
        u32 byte = (u32)(n >> 6) * 8192 + SW128((u32)((n & 63) * 128 + k * 2));
        *(__half*)(g_B4rh + byte) = __float2half_rn(ck * fr);
        *(__half*)(g_B4ih + byte) = __float2half_rn(ck * fi);
    }
}

// ---------------------------------------------------------------------------
// Step 1 (HMMA fp16, split-K over ny): per (b, nx-quad, z): partial over
// chunks 4z..4z+3. z=0 -> g_S1, z=1 -> g_S1b. Grid 1024.
// smem: AH@0(16K) AL@16K BH@32K(8K) = 40KB, 128 threads
// ---------------------------------------------------------------------------
__global__ __launch_bounds__(128) void k_step1_mma(const float* __restrict__ x) {
    extern __shared__ char smem[];
    u32 sb = smem_u32(smem);
    const u32 sAH = sb, sAL = sb + 16384, sBH = sb + 32768;
    int tid = threadIdx.x, w = tid >> 5, lane = tid & 31;
    int nx0 = blockIdx.x * 4, b = blockIdx.y, z = blockIdx.z;

    const float* xrow = x + ((size_t)(b * 512 + nx0 + w)) * 512 * 32 + lane;
    int mrow = w * 32 + lane;

    float acc[2][8][4] = {};

    for (int cc = 0; cc < 4; ++cc) {
        int c = z * 4 + cc;
        {
            const float4* sh = (const float4*)(g_B1h + c * 8192);
            float4* dh = (float4*)(smem + 32768);
#pragma unroll
            for (int t = 0; t < 4; ++t) dh[tid + 128 * t] = sh[tid + 128 * t];
        }
        {
            const float* xc = xrow + (size_t)c * 64 * 32;
#pragma unroll 8
            for (int j2 = 0; j2 < 32; ++j2) {
                float v0 = xc[(2 * j2) * 32];
                float v1 = xc[(2 * j2 + 1) * 32];
                u32 hp, lp;
                split_pair_f16(v0, v1, hp, lp);
                u32 off = SW128((u32)(mrow * 128 + j2 * 4));
                *(u32*)(smem + off) = hp;
                *(u32*)(smem + 16384 + off) = lp;
            }
        }
        __syncthreads();

#pragma unroll
        for (int kk = 0; kk < 4; ++kk) {
            u32 ah[2][4], al[2][4], bh[8][2];
#pragma unroll
            for (int mt = 0; mt < 2; ++mt) {
                u32 row = w * 32 + mt * 16 + (lane & 15);
                u32 blk = kk * 2 + (lane >> 4);
                u32 off = SW128(row * 128 + blk * 16);
                ldsm_x4(ah[mt], sAH + off);
                ldsm_x4(al[mt], sAL + off);
            }
#pragma unroll
            for (int nt = 0; nt < 8; ++nt) {
                u32 row = nt * 8 + (lane & 7);
                u32 blk = kk * 2 + ((lane >> 3) & 1);
                u32 off = SW128(row * 128 + blk * 16);
                ldsm_x2(bh[nt], sBH + off);
            }
#pragma unroll
            for (int mt = 0; mt < 2; ++mt)
#pragma unroll
                for (int nt = 0; nt < 8; ++nt) {
                    mma_f16(acc[mt][nt], ah[mt], bh[nt]);
                    mma_f16(acc[mt][nt], al[mt], bh[nt]);
                }
        }
        __syncthreads();
    }

    int g = lane >> 2, t4 = lane & 3;
    float* obase = (z ? g_S1b : g_S1) + ((size_t)(b * 512 + nx0 + w)) * 64 * 32;
#pragma unroll
    for (int mt = 0; mt < 2; ++mt)
#pragma unroll
        for (int nt = 0; nt < 8; ++nt) {
            int dv1 = mt * 16 + g, dv2 = dv1 + 8;
            int ky0 = nt * 8 + 2 * t4;
            obase[ky0 * 32 + dv1]       = acc[mt][nt][0];
            obase[(ky0 + 1) * 32 + dv1] = acc[mt][nt][1];
            obase[ky0 * 32 + dv2]       = acc[mt][nt][2];
            obase[(ky0 + 1) * 32 + dv2] = acc[mt][nt][3];
        }
}

// ---------------------------------------------------------------------------
// Step 2 (HMMA fp16, split-K over nx): per (b, ky, z): partial over chunks 4z..4z+3.
// A staging sums step-1 partials. z=0 -> S2r/S2i, z=1 -> S2r2/S2i2.
// smem: AH@0(4K) AL@4K BH@8K(16K) = 24KB
// ---------------------------------------------------------------------------
__global__ __launch_bounds__(128) void k_step2n() {
    extern __shared__ char smem[];
    u32 sb = smem_u32(smem);
    const u32 sAH = sb, sAL = sb + 4096, sBH = sb + 8192;
    int tid = threadIdx.x, w = tid >> 5, lane = tid & 31;
    int ky = blockIdx.x, b = blockIdx.y, z = blockIdx.z;
    int dv = tid & 31, jg = tid >> 5;
    size_t s1off = (size_t)b * 512 * 2048 + (size_t)ky * 32 + dv;
    const float* s1a = g_S1 + s1off;
    const float* s1b = g_S1b + s1off;

    float acc[2][4][4] = {};   // [mt][nt_local]

    for (int cc = 0; cc < 4; ++cc) {
        int c = z * 4 + cc;
        {
            const float4* sh = (const float4*)(g_B2h + c * 16384);
            float4* dh = (float4*)(smem + 8192);
#pragma unroll
            for (int t = 0; t < 8; ++t) dh[tid + 128 * t] = sh[tid + 128 * t];
        }
        {
            size_t coff = (size_t)(c * 64) * 2048;
#pragma unroll
            for (int it = 0; it < 8; ++it) {
                int j = jg + 4 * it;
                float v0 = s1a[coff + (2 * j) * 2048] + s1b[coff + (2 * j) * 2048];
                float v1 = s1a[coff + (2 * j + 1) * 2048] + s1b[coff + (2 * j + 1) * 2048];
                u32 hp, lp;
                split_pair_f16(v0, v1, hp, lp);
                u32 off = SW128((u32)(dv * 128 + j * 4));
                *(u32*)(smem + off) = hp;
                *(u32*)(smem + 4096 + off) = lp;
            }
        }
        __syncthreads();

#pragma unroll
        for (int kk = 0; kk < 4; ++kk) {
            u32 ah[2][4], al[2][4];
#pragma unroll
            for (int mt = 0; mt < 2; ++mt) {
                u32 row = mt * 16 + (lane & 15);
                u32 blk = kk * 2 + (lane >> 4);
                u32 off = SW128(row * 128 + blk * 16);
                ldsm_x4(ah[mt], sAH + off);
                ldsm_x4(al[mt], sAL + off);
            }
#pragma unroll
            for (int nt = 0; nt < 4; ++nt) {
                u32 row = (w * 4 + nt) * 8 + (lane & 7);
                u32 blk = kk * 2 + ((lane >> 3) & 1);
                u32 off = SW128(row * 128 + blk * 16);
                u32 bh[2];
                ldsm_x2(bh, sBH + off);
#pragma unroll
                for (int mt = 0; mt < 2; ++mt) {
                    mma_f16(acc[mt][nt], ah[mt], bh);
                    mma_f16(acc[mt][nt], al[mt], bh);
                }
            }
        }
        __syncthreads();
    }

    int g = lane >> 2, t4 = lane & 3;
    float* dr = z ? g_S2r2 : g_S2r;
    float* di = z ? g_S2i2 : g_S2i;
#pragma unroll
    for (int nt = 0; nt < 4; ++nt) {
        int col = (w * 4 + nt) * 8 + 2 * t4;        // 0..127
        int imag = col >> 6;
        int kx = col & 63;
        float* dst = imag ? di : dr;
        size_t base = ((size_t)(b * 64 + kx) * 64 + ky) * 32;
#pragma unroll
        for (int mt = 0; mt < 2; ++mt) {
            int dv1 = mt * 16 + g, dv2 = dv1 + 8;
            dst[base + dv1]            = acc[mt][nt][0];
            dst[base + 2048 + dv1]     = acc[mt][nt][1];
            dst[base + dv2]            = acc[mt][nt][2];
            dst[base + 2048 + dv2]     = acc[mt][nt][3];
        }
    }
}

// ---------------------------------------------------------------------------
// Step 3: per-mode complex channel mix. z=4 split, 2 ic per block:
// X (summed split-K partials) staged ONCE, R staged per ic.
// ---------------------------------------------------------------------------
__global__ __launch_bounds__(256) void k_step3(const float* __restrict__ Rr,
                                               const float* __restrict__ Ri) {
    __shared__ float Xr[4 * 16 * 33], Xi[4 * 16 * 33];
    __shared__ float Sr[4 * 32 * 16], Si[4 * 32 * 16];
    __shared__ float Yr[64 * 4], Yi[64 * 4];
    int kx = blockIdx.x, ky0 = blockIdx.y * 16, z = blockIdx.z;
    int tid = threadIdx.x;
    int lane = tid & 31, w = tid >> 5;

    // stage X once (sum of split-K partials)
#pragma unroll
    for (int r = 0; r < 8; ++r) {
        int row = w * 8 + r;
        int e = row >> 4, u = row & 15;
        size_t src = (((size_t)e * KXX + kx) * KYY + ky0 + u) * DVV + lane;
        Xr[(e * 16 + u) * 33 + lane] = g_S2r[src] + g_S2r2[src];
        Xi[(e * 16 + u) * 33 + lane] = g_S2i[src] + g_S2i2[src];
    }

    int u = tid & 15, e = (tid >> 4) & 3, ii = tid >> 6;

    for (int ic2 = 0; ic2 < 2; ++ic2) {
        int ic = z * 2 + ic2;
        // stage R for this ic
#pragma unroll
        for (int t = 0; t < 8; ++t) {
            int flat = tid + 256 * t;
            int row = flat >> 4, uu = flat & 15;
            int i4 = row >> 5, j = row & 31;
            size_t src = (((size_t)(ic * 4 + i4) * DVV + j) * KXX + kx) * KYY + ky0 + uu;
            Sr[(i4 * 32 + j) * 16 + uu] = Rr[src];
            Si[(i4 * 32 + j) * 16 + uu] = Ri[src];
        }
        __syncthreads();

        float ar = 0.f, ai = 0.f;
#pragma unroll 8
        for (int j = 0; j < 32; ++j) {
            float xr = Xr[(e * 16 + u) * 33 + j];
            float xi = Xi[(e * 16 + u) * 33 + j];
            float rr = Sr[(ii * 32 + j) * 16 + u];
            float ri = Si[(ii * 32 + j) * 16 + u];
            ar = fmaf(rr, xr, ar);
            ar = fmaf(-ri, xi, ar);
            ai = fmaf(rr, xi, ai);
            ai = fmaf(ri, xr, ai);
        }
        Yr[(e * 16 + u) * 4 + ii] = ar;
        Yi[(e * 16 + u) * 4 + ii] = ai;
        __syncthreads();

        if (tid < 128) {
            int row = tid & 63, which = tid >> 6;
            int ee = row >> 4, uu = row & 15;
            float4 v = ((const float4*)(which ? Yi : Yr))[row];
            size_t dst = (((size_t)ee * KYY + ky0 + uu) * KXX + kx) * DVV + ic * 4;
            *(float4*)((which ? g_S3i : g_S3r) + dst) = v;
        }
        __syncthreads();
    }
}

// ---------------------------------------------------------------------------
// Step 4 (HMMA fp16, split over r/i contraction): per (b, ky, z):
// z=0: sum_kx Ar·Br -> g_S4;  z=1: sum_kx Ai·Bi -> g_S4b.
// smem: AH@0(4K) AL@4K BH@8K(8K) = 16KB
// ---------------------------------------------------------------------------
__global__ __launch_bounds__(128) void k_step4n() {
    extern __shared__ char smem[];
    u32 sb = smem_u32(smem);
    const u32 sAH = sb, sAL = sb + 4096, sBH = sb + 8192;
    int tid = threadIdx.x, w = tid >> 5, lane = tid & 31;
    int ky = blockIdx.x, b = blockIdx.y, z = blockIdx.z;
    int dv = tid & 31, jg = tid >> 5;

    {
        size_t base = ((size_t)(b * 64 + ky) * 64) * 32 + dv;
        const float* s3 = (z ? g_S3i : g_S3r) + base;
#pragma unroll
        for (int it = 0; it < 8; ++it) {
            int j = jg + 4 * it;            // kx pair 0..31
            u32 off = SW128((u32)(dv * 128 + j * 4));
            u32 hp, lp;
            split_pair_f16(s3[(2 * j) * 32], s3[(2 * j + 1) * 32], hp, lp);
            *(u32*)(smem + off) = hp;
            *(u32*)(smem + 4096 + off) = lp;
        }
    }

    const char* Bsrc = z ? g_B4ih : g_B4rh;
    float* Dout = z ? g_S4b : g_S4;
    int g = lane >> 2, t4 = lane & 3;

    for (int p = 0; p < 8; ++p) {
        {
            const float4* s0 = (const float4*)(Bsrc + p * 8192);
#pragma unroll
            for (int t = 0; t < 4; ++t)
                ((float4*)(smem + 8192))[tid + 128 * t] = s0[tid + 128 * t];
        }
        __syncthreads();

        float acc[2][2][4] = {};    // [mt][nt_local]
#pragma unroll
        for (int kk = 0; kk < 4; ++kk) {
            u32 ah[2][4], al[2][4];
#pragma unroll
            for (int mt = 0; mt < 2; ++mt) {
                u32 row = mt * 16 + (lane & 15);
                u32 blk = kk * 2 + (lane >> 4);
                u32 off = SW128(row * 128 + blk * 16);
                ldsm_x4(ah[mt], sAH + off);
                ldsm_x4(al[mt], sAL + off);
            }
#pragma unroll
            for (int nt = 0; nt < 2; ++nt) {
                u32 row = (w * 2 + nt) * 8 + (lane & 7);
                u32 blk = kk * 2 + ((lane >> 3) & 1);
                u32 off = SW128(row * 128 + blk * 16);
                u32 bh[2];
                ldsm_x2(bh, sBH + off);
#pragma unroll
                for (int mt = 0; mt < 2; ++mt) {
                    mma_f16(acc[mt][nt], ah[mt], bh);
                    mma_f16(acc[mt][nt], al[mt], bh);
                }
            }
        }
#pragma unroll
        for (int nt = 0; nt < 2; ++nt) {
            int nx = p * 64 + (w * 2 + nt) * 8 + 2 * t4;
            size_t base = ((size_t)(b * 512 + nx) * 64 + ky) * 32;
#pragma unroll
            for (int mt = 0; mt < 2; ++mt) {
                int dv1 = mt * 16 + g, dv2 = dv1 + 8;
                Dout[base + dv1]        = acc[mt][nt][0];
                Dout[base + 2048 + dv1] = acc[mt][nt][1];
                Dout[base + dv2]        = acc[mt][nt][2];
                Dout[base + 2048 + dv2] = acc[mt][nt][3];
            }
        }
        __syncthreads();
    }
}

// ---------------------------------------------------------------------------
// Step 5 (HMMA fp16, N-split over passes): per (b, nx-quad, z): passes 4z..4z+3.
// A staging sums the two step-4 partials. Grid 1024.
// smem: AH@0(16K) AL@16K BH@32K(8K) = 40KB, 128 threads
// ---------------------------------------------------------------------------
__global__ __launch_bounds__(128) void k_step5_mma(float* __restrict__ out) {
    extern __shared__ char smem[];
    u32 sb = smem_u32(smem);
    const u32 sAH = sb, sAL = sb + 16384, sBH = sb + 32768;
    int tid = threadIdx.x, w = tid >> 5, lane = tid & 31;
    int nx0 = blockIdx.x * 4, b = blockIdx.y, z = blockIdx.z;

    {
        int mrow = w * 32 + lane;
        size_t rowoff = ((size_t)(b * 512 + nx0 + w)) * 64 * 32 + lane;
        const float* s4a = g_S4 + rowoff;
        const float* s4b = g_S4b + rowoff;
#pragma unroll 8
        for (int k2 = 0; k2 < 32; ++k2) {
            float v0 = s4a[(2 * k2) * 32] + s4b[(2 * k2) * 32];
            float v1 = s4a[(2 * k2 + 1) * 32] + s4b[(2 * k2 + 1) * 32];
            u32 hp, lp;
            split_pair_f16(v0, v1, hp, lp);
            u32 off = SW128((u32)(mrow * 128 + k2 * 4));
            *(u32*)(smem + off) = hp;
            *(u32*)(smem + 16384 + off) = lp;
        }
    }
    __syncthreads();

    u32 ah[2][4][4], al[2][4][4];
#pragma unroll
    for (int mt = 0; mt < 2; ++mt)
#pragma unroll
        for (int kk = 0; kk < 4; ++kk) {
            u32 row = w * 32 + mt * 16 + (lane & 15);
            u32 blk = kk * 2 + (lane >> 4);
            u32 off = SW128(row * 128 + blk * 16);
            ldsm_x4(ah[mt][kk], sAH + off);
            ldsm_x4(al[mt][kk], sAL + off);
        }

    int g = lane >> 2, t4 = lane & 3;
    float* obase = out + ((size_t)(b * 512 + nx0 + w)) * 512 * 32;

    for (int pp = 0; pp < 4; ++pp) {
        int p = z * 4 + pp;
        __syncthreads();
        {
            const float4* sh = (const float4*)(g_Bth + p * 8192);
            float4* dh = (float4*)(smem + 32768);
#pragma unroll
            for (int t = 0; t < 4; ++t) dh[tid + 128 * t] = sh[tid + 128 * t];
        }
        __syncthreads();

#pragma unroll
        for (int nt = 0; nt < 8; ++nt) {
            u32 bh[4][2];
#pragma unroll
            for (int kk = 0; kk < 4; ++kk) {
                u32 row = nt * 8 + (lane & 7);
                u32 blk = kk * 2 + ((lane >> 3) & 1);
                u32 off = SW128(row * 128 + blk * 16);
                ldsm_x2(bh[kk], sBH + off);
            }
            float acc[2][4] = {};
#pragma unroll
            for (int kk = 0; kk < 4; ++kk)
#pragma unroll
                for (int mt = 0; mt < 2; ++mt) {
                    mma_f16(acc[mt], ah[mt][kk], bh[kk]);
                    mma_f16(acc[mt], al[mt][kk], bh[kk]);
                }
#pragma unroll
            for (int mt = 0; mt < 2; ++mt) {
                int dv1 = mt * 16 + g, dv2 = dv1 + 8;
                int ny0 = p * 64 + nt * 8 + 2 * t4;
                obase[(size_t)ny0 * 32 + dv1]       = acc[mt][0];
                obase[(size_t)(ny0 + 1) * 32 + dv1] = acc[mt][1];
                obase[(size_t)ny0 * 32 + dv2]       = acc[mt][2];
                obase[(size_t)(ny0 + 1) * 32 + dv2] = acc[mt][3];
            }
        }
    }
}

// ---------------------------------------------------------------------------
extern "C" void kernel_launch(void* const* d_in, const int* in_sizes, int n_in,
                              void* d_out, int out_size) {
    const float* x  = (const float*)d_in[0];
    const float* Rr = (const float*)d_in[1];
    const float* Ri = (const float*)d_in[2];
    float* out = (float*)d_out;

    k_precompute<<<128, 256>>>();
    k_step1_mma<<<dim3(128, BB, 2), 128, 40960>>>(x);
    k_step2n<<<dim3(64, BB, 2), 128, 24576>>>();
    k_step3<<<dim3(KXX, KYY / 16, 4), 256>>>(Rr, Ri);
    k_step4n<<<dim3(64, BB, 2), 128, 16384>>>();
    k_step5_mma<<<dim3(128, BB, 2), 128, 40960>>>(out);
}

// round 16
// speedup vs baseline: 1.0241x; 1.0241x over previous
#include <cuda_runtime.h>
#include <cuda_fp16.h>
#include <math.h>
#include <stdint.h>

typedef unsigned long long u64;
typedef unsigned int u32;

#define BB  4
#define NXX 512
#define NYY 512
#define DVV 32
#define KXX 64
#define KYY 64
#define PI_F 3.14159265358979323846f

#define SW128(o) ((o) ^ (((o) >> 3) & 0x70))

__device__ __forceinline__ u32 smem_u32(const void* p) {
    u32 a;
    asm("{ .reg .u64 t; cvta.to.shared.u64 t, %1; cvt.u32.u64 %0, t; }" : "=r"(a) : "l"(p));
    return a;
}
__device__ __forceinline__ void cp16(u32 dst, const void* src) {
    asm volatile("cp.async.cg.shared.global [%0], [%1], 16;" :: "r"(dst), "l"(src));
}
#define CP_COMMIT_WAIT() do { \
    asm volatile("cp.async.commit_group;"); \
    asm volatile("cp.async.wait_group 0;"); \
} while (0)

__device__ __forceinline__ void ldsm_x4(u32* r, u32 addr) {
    asm volatile("ldmatrix.sync.aligned.m8n8.x4.shared.b16 {%0,%1,%2,%3}, [%4];"
                 : "=r"(r[0]), "=r"(r[1]), "=r"(r[2]), "=r"(r[3]) : "r"(addr));
}
__device__ __forceinline__ void ldsm_x2(u32* r, u32 addr) {
    asm volatile("ldmatrix.sync.aligned.m8n8.x2.shared.b16 {%0,%1}, [%2];"
                 : "=r"(r[0]), "=r"(r[1]) : "r"(addr));
}
__device__ __forceinline__ void mma_f16(float* d, const u32* a, const u32* b) {
    asm volatile("mma.sync.aligned.m16n8k16.row.col.f32.f16.f16.f32 "
                 "{%0,%1,%2,%3}, {%4,%5,%6,%7}, {%8,%9}, {%0,%1,%2,%3};"
                 : "+f"(d[0]), "+f"(d[1]), "+f"(d[2]), "+f"(d[3])
                 : "r"(a[0]), "r"(a[1]), "r"(a[2]), "r"(a[3]), "r"(b[0]), "r"(b[1]));
}
// fp16 hi/lo split of a pair: hp = rn(f16) pair; lp = rn(v - h) pair.
__device__ __forceinline__ void split_pair_f16(float v0, float v1, u32 &hp, u32 &lp) {
    asm("cvt.rn.f16x2.f32 %0, %1, %2;" : "=r"(hp) : "f"(v1), "f"(v0));
    __half2 h2 = *reinterpret_cast<__half2*>(&hp);
    float l0 = v0 - __low2float(h2);
    float l1 = v1 - __high2float(h2);
    asm("cvt.rn.f16x2.f32 %0, %1, %2;" : "=r"(lp) : "f"(l1), "f"(l0));
}

// fp16 B operands as smem tile images (SW128 rows)
__device__ __align__(16) char g_B1h[KYY*NYY*2];     // step1: 8 chunks [64 ky][64 ny]
__device__ __align__(16) char g_Bth[NYY*KYY*2];     // step5: 8 passes [64 ny][64 ky]
__device__ __align__(16) char g_B2h[2*KXX*NXX*2];   // step2: 8 chunks [128 (kx r|i)][64 nx]
__device__ __align__(16) char g_B4rh[NXX*KXX*2];    // step4: 8 passes [64 nx][64 kx] real
__device__ __align__(16) char g_B4ih[NXX*KXX*2];    // step4: imag

// Scratch
__device__ __align__(16) float g_S1 [(size_t)BB*NXX*KYY*DVV];  // step1 partial z=0
__device__ __align__(16) float g_S1b[(size_t)BB*NXX*KYY*DVV];  // step1 partial z=1
__device__ __align__(16) float g_S2r [(size_t)BB*KXX*KYY*DVV]; // step2 split-K partials
__device__ __align__(16) float g_S2i [(size_t)BB*KXX*KYY*DVV];
__device__ __align__(16) float g_S2r2[(size_t)BB*KXX*KYY*DVV];
__device__ __align__(16) float g_S2i2[(size_t)BB*KXX*KYY*DVV];
__device__ __align__(16) float g_S3r[(size_t)BB*KYY*KXX*DVV];  // [b][ky][kx][dv]
__device__ __align__(16) float g_S3i[(size_t)BB*KYY*KXX*DVV];
__device__ __align__(16) float g_S4 [(size_t)BB*NXX*KYY*DVV];  // real-contraction partial
__device__ __align__(16) float g_S4b[(size_t)BB*NXX*KYY*DVV];  // imag-contraction partial

// ---------------------------------------------------------------------------
__global__ void k_precompute() {
    int idx = blockIdx.x * blockDim.x + threadIdx.x;
    if (idx >= KXX * NXX) return;
    int k = idx >> 9;          // 0..63
    int n = idx & 511;         // 0..511

    float sk = (k == 0) ? sqrtf(1.0f / 512.0f) : sqrtf(2.0f / 512.0f);
    int m = (k * (2 * n + 1)) & 2047;
    float mm1 = (float)((m > 1024) ? (2048 - m) : m);
    float Ckn = sk * cosf(PI_F * mm1 / 1024.0f);
    {
        __half h = __float2half_rn(Ckn);
        u32 byte1 = (u32)(n >> 6) * 8192 + SW128((u32)(k * 128 + (n & 63) * 2));
        *(__half*)(g_B1h + byte1) = h;
        u32 byte5 = SW128((u32)(n * 128 + k * 2));
        *(__half*)(g_Bth + byte5) = h;
    }

    int mm = (k * n) & 511;
    float ang = 2.0f * PI_F * (float)mm / 512.0f;
    float isq = sqrtf(1.0f / 512.0f);
    float s, c;
    sincosf(ang, &s, &c);
    float fr = c * isq;
    float fi = -s * isq;
    float ck = (k == 0) ? 1.0f : 2.0f;

    {
        u32 cb = (u32)(n >> 6) * 16384;
        u32 br = cb + SW128((u32)(k * 128 + (n & 63) * 2));
        *(__half*)(g_B2h + br) = __float2half_rn(fr);
        u32 bi = cb + SW128((u32)((64 + k) * 128 + (n & 63) * 2));
        *(__half*)(g_B2h + bi) = __float2half_rn(fi);
    }
    {
        u32 byte = (u32)(n >> 6) * 8192 + SW128((u32)((n & 63) * 128 + k * 2));
        *(__half*)(g_B4rh + byte) = __float2half_rn(ck * fr);
        *(__half*)(g_B4ih + byte) = __float2half_rn(ck * fi);
    }
}

// ---------------------------------------------------------------------------
// Step 1 (HMMA fp16, split-K over ny): per (b, nx-quad, z): partial over
// chunks 4z..4z+3. z=0 -> g_S1, z=1 -> g_S1b. Grid 1024.
// smem: AH@0(16K) AL@16K BH@32K(8K) = 40KB, 128 threads
// ---------------------------------------------------------------------------
__global__ __launch_bounds__(128) void k_step1_mma(const float* __restrict__ x) {
    extern __shared__ char smem[];
    u32 sb = smem_u32(smem);
    const u32 sAH = sb, sAL = sb + 16384, sBH = sb + 32768;
    int tid = threadIdx.x, w = tid >> 5, lane = tid & 31;
    int nx0 = blockIdx.x * 4, b = blockIdx.y, z = blockIdx.z;

    const float* xrow = x + ((size_t)(b * 512 + nx0 + w)) * 512 * 32 + lane;
    int mrow = w * 32 + lane;

    float acc[2][8][4] = {};

    for (int cc = 0; cc < 4; ++cc) {
        int c = z * 4 + cc;
        // async B chunk copy (overlaps with A staging below)
#pragma unroll
        for (int t = 0; t < 4; ++t) {
            u32 o16 = (u32)(tid + 128 * t) * 16;
            cp16(sBH + o16, g_B1h + c * 8192 + o16);
        }
        {
            const float* xc = xrow + (size_t)c * 64 * 32;
#pragma unroll 8
            for (int j2 = 0; j2 < 32; ++j2) {
                float v0 = xc[(2 * j2) * 32];
                float v1 = xc[(2 * j2 + 1) * 32];
                u32 hp, lp;
                split_pair_f16(v0, v1, hp, lp);
                u32 off = SW128((u32)(mrow * 128 + j2 * 4));
                *(u32*)(smem + off) = hp;
                *(u32*)(smem + 16384 + off) = lp;
            }
        }
        CP_COMMIT_WAIT();
        __syncthreads();

#pragma unroll
        for (int kk = 0; kk < 4; ++kk) {
            u32 ah[2][4], al[2][4], bh[8][2];
#pragma unroll
            for (int mt = 0; mt < 2; ++mt) {
                u32 row = w * 32 + mt * 16 + (lane & 15);
                u32 blk = kk * 2 + (lane >> 4);
                u32 off = SW128(row * 128 + blk * 16);
                ldsm_x4(ah[mt], sAH + off);
                ldsm_x4(al[mt], sAL + off);
            }
#pragma unroll
            for (int nt = 0; nt < 8; ++nt) {
                u32 row = nt * 8 + (lane & 7);
                u32 blk = kk * 2 + ((lane >> 3) & 1);
                u32 off = SW128(row * 128 + blk * 16);
                ldsm_x2(bh[nt], sBH + off);
            }
#pragma unroll
            for (int mt = 0; mt < 2; ++mt)
#pragma unroll
                for (int nt = 0; nt < 8; ++nt) {
                    mma_f16(acc[mt][nt], ah[mt], bh[nt]);
                    mma_f16(acc[mt][nt], al[mt], bh[nt]);
                }
        }
        __syncthreads();
    }

    int g = lane >> 2, t4 = lane & 3;
    float* obase = (z ? g_S1b : g_S1) + ((size_t)(b * 512 + nx0 + w)) * 64 * 32;
#pragma unroll
    for (int mt = 0; mt < 2; ++mt)
#pragma unroll
        for (int nt = 0; nt < 8; ++nt) {
            int dv1 = mt * 16 + g, dv2 = dv1 + 8;
            int ky0 = nt * 8 + 2 * t4;
            obase[ky0 * 32 + dv1]       = acc[mt][nt][0];
            obase[(ky0 + 1) * 32 + dv1] = acc[mt][nt][1];
            obase[ky0 * 32 + dv2]       = acc[mt][nt][2];
            obase[(ky0 + 1) * 32 + dv2] = acc[mt][nt][3];
        }
}

// ---------------------------------------------------------------------------
// Step 2 (HMMA fp16, split-K over nx): per (b, ky, z): partial over chunks 4z..4z+3.
// A staging sums step-1 partials. z=0 -> S2r/S2i, z=1 -> S2r2/S2i2.
// smem: AH@0(4K) AL@4K BH@8K(16K) = 24KB
// ---------------------------------------------------------------------------
__global__ __launch_bounds__(128) void k_step2n() {
    extern __shared__ char smem[];
    u32 sb = smem_u32(smem);
    const u32 sAH = sb, sAL = sb + 4096, sBH = sb + 8192;
    int tid = threadIdx.x, w = tid >> 5, lane = tid & 31;
    int ky = blockIdx.x, b = blockIdx.y, z = blockIdx.z;
    int dv = tid & 31, jg = tid >> 5;
    size_t s1off = (size_t)b * 512 * 2048 + (size_t)ky * 32 + dv;
    const float* s1a = g_S1 + s1off;
    const float* s1b = g_S1b + s1off;

    float acc[2][4][4] = {};   // [mt][nt_local]

    for (int cc = 0; cc < 4; ++cc) {
        int c = z * 4 + cc;
#pragma unroll
        for (int t = 0; t < 8; ++t) {
            u32 o16 = (u32)(tid + 128 * t) * 16;
            cp16(sBH + o16, g_B2h + c * 16384 + o16);
        }
        {
            size_t coff = (size_t)(c * 64) * 2048;
#pragma unroll
            for (int it = 0; it < 8; ++it) {
                int j = jg + 4 * it;
                float v0 = s1a[coff + (2 * j) * 2048] + s1b[coff + (2 * j) * 2048];
                float v1 = s1a[coff + (2 * j + 1) * 2048] + s1b[coff + (2 * j + 1) * 2048];
                u32 hp, lp;
                split_pair_f16(v0, v1, hp, lp);
                u32 off = SW128((u32)(dv * 128 + j * 4));
                *(u32*)(smem + off) = hp;
                *(u32*)(smem + 4096 + off) = lp;
            }
        }
        CP_COMMIT_WAIT();
        __syncthreads();

#pragma unroll
        for (int kk = 0; kk < 4; ++kk) {
            u32 ah[2][4], al[2][4];
#pragma unroll
            for (int mt = 0; mt < 2; ++mt) {
                u32 row = mt * 16 + (lane & 15);
                u32 blk = kk * 2 + (lane >> 4);
                u32 off = SW128(row * 128 + blk * 16);
                ldsm_x4(ah[mt], sAH + off);
                ldsm_x4(al[mt], sAL + off);
            }
#pragma unroll
            for (int nt = 0; nt < 4; ++nt) {
                u32 row = (w * 4 + nt) * 8 + (lane & 7);
                u32 blk = kk * 2 + ((lane >> 3) & 1);
                u32 off = SW128(row * 128 + blk * 16);
                u32 bh[2];
                ldsm_x2(bh, sBH + off);
#pragma unroll
                for (int mt = 0; mt < 2; ++mt) {
                    mma_f16(acc[mt][nt], ah[mt], bh);
                    mma_f16(acc[mt][nt], al[mt], bh);
                }
            }
        }
        __syncthreads();
    }

    int g = lane >> 2, t4 = lane & 3;
    float* dr = z ? g_S2r2 : g_S2r;
    float* di = z ? g_S2i2 : g_S2i;
#pragma unroll
    for (int nt = 0; nt < 4; ++nt) {
        int col = (w * 4 + nt) * 8 + 2 * t4;        // 0..127
        int imag = col >> 6;
        int kx = col & 63;
        float* dst = imag ? di : dr;
        size_t base = ((size_t)(b * 64 + kx) * 64 + ky) * 32;
#pragma unroll
        for (int mt = 0; mt < 2; ++mt) {
            int dv1 = mt * 16 + g, dv2 = dv1 + 8;
            dst[base + dv1]            = acc[mt][nt][0];
            dst[base + 2048 + dv1]     = acc[mt][nt][1];
            dst[base + dv2]            = acc[mt][nt][2];
            dst[base + 2048 + dv2]     = acc[mt][nt][3];
        }
    }
}

// ---------------------------------------------------------------------------
// Step 3 (R14 z=8): per-mode complex channel mix; X staging sums split-K partials.
// ---------------------------------------------------------------------------
__global__ __launch_bounds__(256) void k_step3(const float* __restrict__ Rr,
                                               const float* __restrict__ Ri) {
    __shared__ float Xr[4 * 16 * 33], Xi[4 * 16 * 33];
    __shared__ float Sr[4 * 32 * 16], Si[4 * 32 * 16];
    __shared__ float Yr[64 * 4], Yi[64 * 4];
    int kx = blockIdx.x, ky0 = blockIdx.y * 16, ic = blockIdx.z;
    int tid = threadIdx.x;
    int lane = tid & 31, w = tid >> 5;

#pragma unroll
    for (int r = 0; r < 8; ++r) {
        int row = w * 8 + r;
        int e = row >> 4, u = row & 15;
        size_t src = (((size_t)e * KXX + kx) * KYY + ky0 + u) * DVV + lane;
        Xr[(e * 16 + u) * 33 + lane] = g_S2r[src] + g_S2r2[src];
        Xi[(e * 16 + u) * 33 + lane] = g_S2i[src] + g_S2i2[src];
    }
#pragma unroll
    for (int t = 0; t < 8; ++t) {
        int flat = tid + 256 * t;
        int row = flat >> 4, uu = flat & 15;
        int i4 = row >> 5, j = row & 31;
        size_t src = (((size_t)(ic * 4 + i4) * DVV + j) * KXX + kx) * KYY + ky0 + uu;
        Sr[(i4 * 32 + j) * 16 + uu] = Rr[src];
        Si[(i4 * 32 + j) * 16 + uu] = Ri[src];
    }
    __syncthreads();

    int u = tid & 15, e = (tid >> 4) & 3, ii = tid >> 6;
    float ar = 0.f, ai = 0.f;
#pragma unroll 8
    for (int j = 0; j < 32; ++j) {
        float xr = Xr[(e * 16 + u) * 33 + j];
        float xi = Xi[(e * 16 + u) * 33 + j];
        float rr = Sr[(ii * 32 + j) * 16 + u];
        float ri = Si[(ii * 32 + j) * 16 + u];
        ar = fmaf(rr, xr, ar);
        ar = fmaf(-ri, xi, ar);
        ai = fmaf(rr, xi, ai);
        ai = fmaf(ri, xr, ai);
    }
    Yr[(e * 16 + u) * 4 + ii] = ar;
    Yi[(e * 16 + u) * 4 + ii] = ai;
    __syncthreads();

    if (tid < 128) {
        int row = tid & 63, which = tid >> 6;
        int ee = row >> 4, uu = row & 15;
        float4 v = ((const float4*)(which ? Yi : Yr))[row];
        size_t dst = (((size_t)ee * KYY + ky0 + uu) * KXX + kx) * DVV + ic * 4;
        *(float4*)((which ? g_S3i : g_S3r) + dst) = v;
    }
}

// ---------------------------------------------------------------------------
// Step 4 (HMMA fp16, split over r/i contraction): per (b, ky, z):
// z=0: sum_kx Ar·Br -> g_S4;  z=1: sum_kx Ai·Bi -> g_S4b.
// smem: AH@0(4K) AL@4K BH@8K(8K) = 16KB
// ---------------------------------------------------------------------------
__global__ __launch_bounds__(128) void k_step4n() {
    extern __shared__ char smem[];
    u32 sb = smem_u32(smem);
    const u32 sAH = sb, sAL = sb + 4096, sBH = sb + 8192;
    int tid = threadIdx.x, w = tid >> 5, lane = tid & 31;
    int ky = blockIdx.x, b = blockIdx.y, z = blockIdx.z;
    int dv = tid & 31, jg = tid >> 5;

    const char* Bsrc = z ? g_B4ih : g_B4rh;
    // prefetch first B pass
#pragma unroll
    for (int t = 0; t < 4; ++t) {
        u32 o16 = (u32)(tid + 128 * t) * 16;
        cp16(sBH + o16, Bsrc + o16);
    }
    {
        size_t base = ((size_t)(b * 64 + ky) * 64) * 32 + dv;
        const float* s3 = (z ? g_S3i : g_S3r) + base;
#pragma unroll
        for (int it = 0; it < 8; ++it) {
            int j = jg + 4 * it;            // kx pair 0..31
            u32 off = SW128((u32)(dv * 128 + j * 4));
            u32 hp, lp;
            split_pair_f16(s3[(2 * j) * 32], s3[(2 * j + 1) * 32], hp, lp);
            *(u32*)(smem + off) = hp;
            *(u32*)(smem + 4096 + off) = lp;
        }
    }

    float* Dout = z ? g_S4b : g_S4;
    int g = lane >> 2, t4 = lane & 3;

    for (int p = 0; p < 8; ++p) {
        CP_COMMIT_WAIT();
        __syncthreads();

        float acc[2][2][4] = {};    // [mt][nt_local]
#pragma unroll
        for (int kk = 0; kk < 4; ++kk) {
            u32 ah[2][4], al[2][4];
#pragma unroll
            for (int mt = 0; mt < 2; ++mt) {
                u32 row = mt * 16 + (lane & 15);
                u32 blk = kk * 2 + (lane >> 4);
                u32 off = SW128(row * 128 + blk * 16);
                ldsm_x4(ah[mt], sAH + off);
                ldsm_x4(al[mt], sAL + off);
            }
#pragma unroll
            for (int nt = 0; nt < 2; ++nt) {
                u32 row = (w * 2 + nt) * 8 + (lane & 7);
                u32 blk = kk * 2 + ((lane >> 3) & 1);
                u32 off = SW128(row * 128 + blk * 16);
                u32 bh[2];
                ldsm_x2(bh, sBH + off);
#pragma unroll
                for (int mt = 0; mt < 2; ++mt) {
                    mma_f16(acc[mt][nt], ah[mt], bh);
                    mma_f16(acc[mt][nt], al[mt], bh);
                }
            }
        }
        // store pass results, then prefetch next B pass
#pragma unroll
        for (int nt = 0; nt < 2; ++nt) {
            int nx = p * 64 + (w * 2 + nt) * 8 + 2 * t4;
            size_t base = ((size_t)(b * 512 + nx) * 64 + ky) * 32;
#pragma unroll
            for (int mt = 0; mt < 2; ++mt) {
                int dv1 = mt * 16 + g, dv2 = dv1 + 8;
                Dout[base + dv1]        = acc[mt][nt][0];
                Dout[base + 2048 + dv1] = acc[mt][nt][1];
                Dout[base + dv2]        = acc[mt][nt][2];
                Dout[base + 2048 + dv2] = acc[mt][nt][3];
            }
        }
        __syncthreads();
        if (p < 7) {
#pragma unroll
            for (int t = 0; t < 4; ++t) {
                u32 o16 = (u32)(tid + 128 * t) * 16;
                cp16(sBH + o16, Bsrc + (p + 1) * 8192 + o16);
            }
        }
    }
}

// ---------------------------------------------------------------------------
// Step 5 (HMMA fp16, N-split over passes): per (b, nx-quad, z): passes 4z..4z+3.
// A staging sums the two step-4 partials. Grid 1024.
// smem: AH@0(16K) AL@16K BH@32K(8K) = 40KB, 128 threads
// ---------------------------------------------------------------------------
__global__ __launch_bounds__(128) void k_step5_mma(float* __restrict__ out) {
    extern __shared__ char smem[];
    u32 sb = smem_u32(smem);
    const u32 sAH = sb, sAL = sb + 16384, sBH = sb + 32768;
    int tid = threadIdx.x, w = tid >> 5, lane = tid & 31;
    int nx0 = blockIdx.x * 4, b = blockIdx.y, z = blockIdx.z;

    // prefetch first B pass
#pragma unroll
    for (int t = 0; t < 4; ++t) {
        u32 o16 = (u32)(tid + 128 * t) * 16;
        cp16(sBH + o16, g_Bth + (z * 4) * 8192 + o16);
    }
    {
        int mrow = w * 32 + lane;
        size_t rowoff = ((size_t)(b * 512 + nx0 + w)) * 64 * 32 + lane;
        const float* s4a = g_S4 + rowoff;
        const float* s4b = g_S4b + rowoff;
#pragma unroll 8
        for (int k2 = 0; k2 < 32; ++k2) {
            float v0 = s4a[(2 * k2) * 32] + s4b[(2 * k2) * 32];
            float v1 = s4a[(2 * k2 + 1) * 32] + s4b[(2 * k2 + 1) * 32];
            u32 hp, lp;
            split_pair_f16(v0, v1, hp, lp);
            u32 off = SW128((u32)(mrow * 128 + k2 * 4));
            *(u32*)(smem + off) = hp;
            *(u32*)(smem + 16384 + off) = lp;
        }
    }
    __syncthreads();

    u32 ah[2][4][4], al[2][4][4];
#pragma unroll
    for (int mt = 0; mt < 2; ++mt)
#pragma unroll
        for (int kk = 0; kk < 4; ++kk) {
            u32 row = w * 32 + mt * 16 + (lane & 15);
            u32 blk = kk * 2 + (lane >> 4);
            u32 off = SW128(row * 128 + blk * 16);
            ldsm_x4(ah[mt][kk], sAH + off);
            ldsm_x4(al[mt][kk], sAL + off);
        }

    int g = lane >> 2, t4 = lane & 3;
    float* obase = out + ((size_t)(b * 512 + nx0 + w)) * 512 * 32;

    for (int pp = 0; pp < 4; ++pp) {
        int p = z * 4 + pp;
        CP_COMMIT_WAIT();
        __syncthreads();

#pragma unroll
        for (int nt = 0; nt < 8; ++nt) {
            u32 bh[4][2];
#pragma unroll
            for (int kk = 0; kk < 4; ++kk) {
                u32 row = nt * 8 + (lane & 7);
                u32 blk = kk * 2 + ((lane >> 3) & 1);
                u32 off = SW128(row * 128 + blk * 16);
                ldsm_x2(bh[kk], sBH + off);
            }
            float acc[2][4] = {};
#pragma unroll
            for (int kk = 0; kk < 4; ++kk)
#pragma unroll
                for (int mt = 0; mt < 2; ++mt) {
                    mma_f16(acc[mt], ah[mt][kk], bh[kk]);
                    mma_f16(acc[mt], al[mt][kk], bh[kk]);
                }
#pragma unroll
            for (int mt = 0; mt < 2; ++mt) {
                int dv1 = mt * 16 + g, dv2 = dv1 + 8;
                int ny0 = p * 64 + nt * 8 + 2 * t4;
                obase[(size_t)ny0 * 32 + dv1]       = acc[mt][0];
                obase[(size_t)(ny0 + 1) * 32 + dv1] = acc[mt][1];
                obase[(size_t)ny0 * 32 + dv2]       = acc[mt][2];
                obase[(size_t)(ny0 + 1) * 32 + dv2] = acc[mt][3];
            }
        }
        __syncthreads();
        if (pp < 3) {
#pragma unroll
            for (int t = 0; t < 4; ++t) {
                u32 o16 = (u32)(tid + 128 * t) * 16;
                cp16(sBH + o16, g_Bth + (p + 1) * 8192 + o16);
            }
        }
    }
}

// ---------------------------------------------------------------------------
extern "C" void kernel_launch(void* const* d_in, const int* in_sizes, int n_in,
                              void* d_out, int out_size) {
    const float* x  = (const float*)d_in[0];
    const float* Rr = (const float*)d_in[1];
    const float* Ri = (const float*)d_in[2];
    float* out = (float*)d_out;

    k_precompute<<<128, 256>>>();
    k_step1_mma<<<dim3(128, BB, 2), 128, 40960>>>(x);
    k_step2n<<<dim3(64, BB, 2), 128, 24576>>>();
    k_step3<<<dim3(KXX, KYY / 16, 8), 256>>>(Rr, Ri);
    k_step4n<<<dim3(64, BB, 2), 128, 16384>>>();
    k_step5_mma<<<dim3(128, BB, 2), 128, 40960>>>(out);
}